// round 13
// baseline (speedup 1.0000x reference)
#include <cuda_runtime.h>
#include <cuda_fp16.h>
#include <mma.h>
#include <math.h>

using namespace nvcuda;

#define N_NODES 100000
#define N_EDGES 1600000
#define HID     128
#define CHUNK   128
#define NB      ((N_NODES + CHUNK - 1) / CHUNK)   // 782
#define NPAD    100352                            // 1568 * 64
#define GEMM_SMEM 52224                           // 17408 (A) + 34816 (B/C)

// ---------------- scratch (static device globals; no runtime allocation) ----------------
static __device__ int      g_is64;
static __device__ int      g_deg [N_NODES];
static __device__ int      g_part[NB];
static __device__ int      g_partoff[NB];
static __device__ int      g_off [N_NODES + 1];
static __device__ int      g_cur [N_NODES];
static __device__ int      g_csr_src[N_EDGES];
static __device__ int      g_csr_eid[N_EDGES];
static __device__ __align__(16) float  g_x8 [N_NODES * 8];    // fp32 (self term)
static __device__ __align__(16) __half g_x8h[N_NODES * 8];    // fp16 (gathered)
static __device__ __align__(16) __half g_h1h[NPAD * HID];     // fp16 (pad rows stay zero)
static __device__ __align__(16) __half g_ph [NPAD * HID];     // fp16 (gathered)
static __device__ __align__(16) __half g_qh [NPAD * HID];     // fp16
static __device__ float    g_hg [N_NODES];
// fp16 weights: w2cat [256][128] (rows 0-127 w2l, 128-255 w2r); w_h[m] [128][128] [k][c]
static __device__ __align__(16) __half g_w2cat_h[256 * HID];
static __device__ __align__(16) __half g_w_h[3][HID * HID];

// ---------------- setup: dtype detect + deg clear + x8 + fp16 weights ----------------
__global__ void k_setup(const float* __restrict__ x, const int* __restrict__ ei32,
                        const float* __restrict__ w2l, const float* __restrict__ w2r,
                        const float* __restrict__ wv1, const float* __restrict__ we1) {
    int idx = blockIdx.x * blockDim.x + threadIdx.x;
    int stride = gridDim.x * blockDim.x;
    if (idx == 0) {
        int nz = 0;
        for (int j = 0; j < 256; j++) nz |= ei32[2 * j + 1];
        g_is64 = (nz == 0) ? 1 : 0;   // int64 values < 2^31 -> odd words all zero
    }
    for (int n = idx; n < N_NODES; n += stride) {
        g_deg[n] = 0;
        const float* xr = x + (size_t)n * 7;
        float4 a, b;
        a.x = xr[0]; a.y = xr[1]; a.z = xr[2]; a.w = xr[3];
        b.x = xr[4]; b.y = xr[5]; b.z = xr[6]; b.w = 0.f;
        ((float4*)g_x8)[(size_t)n * 2 + 0] = a;
        ((float4*)g_x8)[(size_t)n * 2 + 1] = b;
        __half2* hp = (__half2*)(g_x8h + (size_t)n * 8);
        hp[0] = __floats2half2_rn(a.x, a.y);
        hp[1] = __floats2half2_rn(a.z, a.w);
        hp[2] = __floats2half2_rn(b.x, b.y);
        hp[3] = __floats2half2_rn(b.z, b.w);
    }
    for (int i = idx; i < 256 * HID; i += stride) {
        int k = i >> 7, c = i & 127;
        float v = (k < 128) ? w2l[k * HID + c] : w2r[(k - 128) * HID + c];
        g_w2cat_h[i] = __float2half_rn(v);
    }
    for (int j = idx; j < 3 * HID * HID; j += stride) {
        int m = j >> 14;
        int e = j & 16383;
        float v = (m == 0) ? wv1[e] : (m == 1) ? we1[e] : we1[16384 + e];
        g_w_h[m][e] = __float2half_rn(v);
    }
}

// degree histogram straight from edge_index
__global__ void k_convert(const void* __restrict__ ei) {
    int i = blockIdx.x * blockDim.x + threadIdx.x;
    int stride = gridDim.x * blockDim.x;
    const int is64 = g_is64;
    for (int e = i; e < N_EDGES; e += stride) {
        int d;
        if (is64) d = (int)((const long long*)ei)[N_EDGES + e];
        else      d = ((const int*)ei)[N_EDGES + e];
        d = min(max(d, 0), N_NODES - 1);
        atomicAdd(&g_deg[d], 1);
    }
}

// ---------------- CSR build ----------------
__global__ void k_scan1() {
    __shared__ int sh[CHUNK];
    int b = blockIdx.x, tid = threadIdx.x;
    int i = b * CHUNK + tid;
    sh[tid] = (i < N_NODES) ? g_deg[i] : 0;
    __syncthreads();
    for (int off = 64; off; off >>= 1) {
        if (tid < off) sh[tid] += sh[tid + off];
        __syncthreads();
    }
    if (tid == 0) g_part[b] = sh[0];
}

__global__ void k_scan2() {
    __shared__ int sh[1024];
    int tid = threadIdx.x;
    int v = (tid < NB) ? g_part[tid] : 0;
    sh[tid] = v;
    __syncthreads();
    for (int off = 1; off < 1024; off <<= 1) {
        int add = (tid >= off) ? sh[tid - off] : 0;
        __syncthreads();
        sh[tid] += add;
        __syncthreads();
    }
    if (tid < NB) g_partoff[tid] = sh[tid] - v;
    if (tid == 1023) g_off[N_NODES] = sh[tid];
}

__global__ void k_scan3() {
    __shared__ int sh[CHUNK];
    int b = blockIdx.x, tid = threadIdx.x;
    int i = b * CHUNK + tid;
    int v = (i < N_NODES) ? g_deg[i] : 0;
    sh[tid] = v;
    __syncthreads();
    for (int off = 1; off < CHUNK; off <<= 1) {
        int add = (tid >= off) ? sh[tid - off] : 0;
        __syncthreads();
        sh[tid] += add;
        __syncthreads();
    }
    if (i < N_NODES) {
        int excl = g_partoff[b] + sh[tid] - v;
        g_off[i] = excl;
        g_cur[i] = excl;
    }
}

// fill CSR, converting directly from edge_index
__global__ void k_fill(const void* __restrict__ ei) {
    int e = blockIdx.x * blockDim.x + threadIdx.x;
    if (e >= N_EDGES) return;
    const int is64 = g_is64;
    int s, d;
    if (is64) {
        const long long* p = (const long long*)ei;
        s = (int)p[e]; d = (int)p[N_EDGES + e];
    } else {
        const int* p = (const int*)ei;
        s = p[e]; d = p[N_EDGES + e];
    }
    s = min(max(s, 0), N_NODES - 1);
    d = min(max(d, 0), N_NODES - 1);
    int pos = atomicAdd(&g_cur[d], 1);
    g_csr_src[pos] = s;
    g_csr_eid[pos] = e;
}

// ---------------- fused SAGE-1: aggregate (fp16 gather) + linear + relu -> h1h ---------
__global__ void k_sage1(const float* __restrict__ w1l, const float* __restrict__ b1,
                        const float* __restrict__ w1r) {
    __shared__ float s_wl[7][HID], s_wr[7][HID], s_b[HID];
    int tid = threadIdx.x;
    for (int j = tid; j < 7 * HID; j += 256) {
        s_wl[j >> 7][j & 127] = w1l[j];
        s_wr[j >> 7][j & 127] = w1r[j];
    }
    if (tid < HID) s_b[tid] = b1[tid];
    __syncthreads();
    int wid = tid >> 5, lane = tid & 31;
    int n = blockIdx.x * 8 + wid;
    if (n >= N_NODES) return;
    int beg = g_off[n], end = g_off[n + 1];
    float a0 = 0.f, a1 = 0.f, a2 = 0.f, a3 = 0.f, a4 = 0.f, a5 = 0.f, a6 = 0.f;
    for (int i = beg + lane; i < end; i += 32) {
        int s = g_csr_src[i];
        uint4 raw = *(const uint4*)(g_x8h + (size_t)s * 8);
        float2 f0 = __half22float2(*(__half2*)&raw.x);
        float2 f1 = __half22float2(*(__half2*)&raw.y);
        float2 f2 = __half22float2(*(__half2*)&raw.z);
        float2 f3 = __half22float2(*(__half2*)&raw.w);
        a0 += f0.x; a1 += f0.y; a2 += f1.x; a3 += f1.y;
        a4 += f2.x; a5 += f2.y; a6 += f3.x;
    }
#pragma unroll
    for (int off = 16; off; off >>= 1) {
        a0 += __shfl_xor_sync(0xFFFFFFFFu, a0, off);
        a1 += __shfl_xor_sync(0xFFFFFFFFu, a1, off);
        a2 += __shfl_xor_sync(0xFFFFFFFFu, a2, off);
        a3 += __shfl_xor_sync(0xFFFFFFFFu, a3, off);
        a4 += __shfl_xor_sync(0xFFFFFFFFu, a4, off);
        a5 += __shfl_xor_sync(0xFFFFFFFFu, a5, off);
        a6 += __shfl_xor_sync(0xFFFFFFFFu, a6, off);
    }
    float inv = 1.f / fmaxf((float)(end - beg), 1.f);
    float m[7] = {a0 * inv, a1 * inv, a2 * inv, a3 * inv, a4 * inv, a5 * inv, a6 * inv};
    const float4* xp = (const float4*)(g_x8 + (size_t)n * 8);
    float4 u = xp[0];
    float4 w = xp[1];
    float xn[7] = {u.x, u.y, u.z, u.w, w.x, w.y, w.z};
#pragma unroll
    for (int j = 0; j < 4; j++) {
        int c = lane + 32 * j;
        float acc = s_b[c];
#pragma unroll
        for (int k = 0; k < 7; k++)
            acc += m[k] * s_wl[k][c] + xn[k] * s_wr[k][c];
        g_h1h[(size_t)n * HID + c] = __float2half_rn(fmaxf(acc, 0.f));
    }
}

// ---------------- fused SAGE-2 + t/p/q: gather + 4 GEMMs + all epilogues ----------------
// h2 never leaves the block: computed via wmma (K=256), written as fp16 into sA,
// then used as the A operand for the t/p/q GEMMs.
__global__ void __launch_bounds__(128) k_gemm_all(
        const float* __restrict__ b2, const float* __restrict__ wg,
        const float* __restrict__ bv1, const float* __restrict__ be1,
        const float* __restrict__ wv2, const float* __restrict__ bv2,
        float* __restrict__ out_pos) {
    extern __shared__ __align__(16) char smem[];
    __half (*sA)[136] = (__half(*)[136])smem;               // 64 x 136 half
    __half (*sB)[136] = (__half(*)[136])(smem + 17408);     // 128 x 136 half
    float  (*sC)[136] = (float (*)[136])(smem + 17408);     // 64 x 136 fp32 (reuse)
    int tid = threadIdx.x;
    int warp = tid >> 5, lane = tid & 31;
    int n0 = blockIdx.x * 64;

    // ---- prologue: gather mean(h1h[neighbors]) into sA (one warp per node, unroll 4)
    for (int r = warp; r < 64; r += 4) {
        int n = n0 + r;
        float4 acc = {0.f, 0.f, 0.f, 0.f};
        float inv = 0.f;
        if (n < N_NODES) {
            int beg = g_off[n], end = g_off[n + 1];
            int i = beg;
            for (; i + 4 <= end; i += 4) {
                int s0 = g_csr_src[i], s1 = g_csr_src[i + 1];
                int s2 = g_csr_src[i + 2], s3 = g_csr_src[i + 3];
                uint2 r0 = *(const uint2*)(g_h1h + (size_t)s0 * HID + lane * 4);
                uint2 r1 = *(const uint2*)(g_h1h + (size_t)s1 * HID + lane * 4);
                uint2 r2 = *(const uint2*)(g_h1h + (size_t)s2 * HID + lane * 4);
                uint2 r3 = *(const uint2*)(g_h1h + (size_t)s3 * HID + lane * 4);
                float2 f;
                f = __half22float2(*(__half2*)&r0.x); acc.x += f.x; acc.y += f.y;
                f = __half22float2(*(__half2*)&r0.y); acc.z += f.x; acc.w += f.y;
                f = __half22float2(*(__half2*)&r1.x); acc.x += f.x; acc.y += f.y;
                f = __half22float2(*(__half2*)&r1.y); acc.z += f.x; acc.w += f.y;
                f = __half22float2(*(__half2*)&r2.x); acc.x += f.x; acc.y += f.y;
                f = __half22float2(*(__half2*)&r2.y); acc.z += f.x; acc.w += f.y;
                f = __half22float2(*(__half2*)&r3.x); acc.x += f.x; acc.y += f.y;
                f = __half22float2(*(__half2*)&r3.y); acc.z += f.x; acc.w += f.y;
            }
            for (; i < end; i++) {
                int s = g_csr_src[i];
                uint2 r0 = *(const uint2*)(g_h1h + (size_t)s * HID + lane * 4);
                float2 f;
                f = __half22float2(*(__half2*)&r0.x); acc.x += f.x; acc.y += f.y;
                f = __half22float2(*(__half2*)&r0.y); acc.z += f.x; acc.w += f.y;
            }
            inv = 1.f / fmaxf((float)(end - beg), 1.f);
        }
        __half2 h01 = __floats2half2_rn(acc.x * inv, acc.y * inv);
        __half2 h23 = __floats2half2_rn(acc.z * inv, acc.w * inv);
        uint2 packed;
        packed.x = *(unsigned*)&h01;
        packed.y = *(unsigned*)&h23;
        *(uint2*)&sA[r][lane * 4] = packed;
    }

    wmma::fragment<wmma::accumulator, 16, 16, 16, float> c[8];
#pragma unroll
    for (int i = 0; i < 8; i++) wmma::fill_fragment(c[i], 0.f);
    wmma::fragment<wmma::matrix_a, 16, 16, 16, __half, wmma::row_major> a;
    wmma::fragment<wmma::matrix_b, 16, 16, 16, __half, wmma::row_major> b;

    // ---- kh = 0: A = mean (sA), B = w2l rows
    {
        const uint4* wsrc = (const uint4*)g_w2cat_h;
        for (int j = tid; j < 128 * 16; j += 128) {
            int r = j >> 4, c4 = j & 15;
            ((uint4*)&sB[r][0])[c4] = wsrc[(size_t)r * 16 + c4];
        }
        __syncthreads();
#pragma unroll
        for (int kt = 0; kt < 8; kt++) {
            wmma::load_matrix_sync(a, &sA[warp * 16][kt * 16], 136);
#pragma unroll
            for (int nt = 0; nt < 8; nt++) {
                wmma::load_matrix_sync(b, &sB[kt * 16][nt * 16], 136);
                wmma::mma_sync(c[nt], a, b, c[nt]);
            }
        }
        __syncthreads();
    }
    // ---- kh = 1: A = h1h rows, B = w2r rows
    {
        const uint4* asrc = (const uint4*)g_h1h;
        for (int j = tid; j < 64 * 16; j += 128) {
            int r = j >> 4, c4 = j & 15;
            ((uint4*)&sA[r][0])[c4] = asrc[(size_t)(n0 + r) * 16 + c4];
        }
        const uint4* wsrc = (const uint4*)g_w2cat_h;
        for (int j = tid; j < 128 * 16; j += 128) {
            int r = j >> 4, c4 = j & 15;
            ((uint4*)&sB[r][0])[c4] = wsrc[(size_t)(128 + r) * 16 + c4];
        }
        __syncthreads();
#pragma unroll
        for (int kt = 0; kt < 8; kt++) {
            wmma::load_matrix_sync(a, &sA[warp * 16][kt * 16], 136);
#pragma unroll
            for (int nt = 0; nt < 8; nt++) {
                wmma::load_matrix_sync(b, &sB[kt * 16][nt * 16], 136);
                wmma::mma_sync(c[nt], a, b, c[nt]);
            }
        }
        __syncthreads();
    }
#pragma unroll
    for (int nt = 0; nt < 8; nt++)
        wmma::store_matrix_sync(&sC[warp * 16][nt * 16], c[nt], 136, wmma::mem_row_major);
    __syncthreads();

    // ---- h2 epilogue: fp16 h2 into sA (stays in smem) + hg = (sC + b2) . wg
    for (int j = tid; j < 64 * 128; j += 128) {
        int r = j >> 7, cc = j & 127;
        float v = sC[r][cc] + __ldg(&b2[cc]);
        sA[r][cc] = __float2half_rn(v);
    }
    for (int r = warp; r < 64; r += 4) {
        float part = 0.f;
#pragma unroll
        for (int j = 0; j < 4; j++) {
            int cc = lane + 32 * j;
            part += (sC[r][cc] + __ldg(&b2[cc])) * __ldg(&wg[cc]);
        }
#pragma unroll
        for (int off = 16; off; off >>= 1)
            part += __shfl_xor_sync(0xFFFFFFFFu, part, off);
        if (lane == 0 && n0 + r < N_NODES) g_hg[n0 + r] = part;
    }
    __syncthreads();

    // ---- t/p/q GEMMs on the in-smem h2 (A fragments preloaded)
    wmma::fragment<wmma::matrix_a, 16, 16, 16, __half, wmma::row_major> af[8];
#pragma unroll
    for (int kt = 0; kt < 8; kt++)
        wmma::load_matrix_sync(af[kt], &sA[warp * 16][kt * 16], 136);

#pragma unroll 1
    for (int m = 0; m < 3; m++) {
        const uint4* wsrc = (const uint4*)g_w_h[m];
        __syncthreads();                       // prior sC reads done before overwrite
        for (int j = tid; j < 128 * 16; j += 128) {
            int r = j >> 4, c4 = j & 15;
            ((uint4*)&sB[r][0])[c4] = wsrc[(size_t)r * 16 + c4];
        }
        __syncthreads();
        wmma::fragment<wmma::accumulator, 16, 16, 16, float> cm[8];
#pragma unroll
        for (int i = 0; i < 8; i++) wmma::fill_fragment(cm[i], 0.f);
#pragma unroll
        for (int kt = 0; kt < 8; kt++) {
#pragma unroll
            for (int nt = 0; nt < 8; nt++) {
                wmma::load_matrix_sync(b, &sB[kt * 16][nt * 16], 136);
                wmma::mma_sync(cm[nt], af[kt], b, cm[nt]);
            }
        }
        __syncthreads();
#pragma unroll
        for (int nt = 0; nt < 8; nt++)
            wmma::store_matrix_sync(&sC[warp * 16][nt * 16], cm[nt], 136, wmma::mem_row_major);
        __syncthreads();
        if (m == 0) {
            // positions: pos = relu(sC + bv1) . wv2 + bv2   (t never materialized)
            for (int r = warp; r < 64; r += 4) {
                float p0 = 0.f, p1 = 0.f, p2 = 0.f;
#pragma unroll
                for (int j = 0; j < 4; j++) {
                    int cc = lane + 32 * j;
                    float tv = fmaxf(sC[r][cc] + __ldg(&bv1[cc]), 0.f);
                    p0 += tv * __ldg(&wv2[cc * 3 + 0]);
                    p1 += tv * __ldg(&wv2[cc * 3 + 1]);
                    p2 += tv * __ldg(&wv2[cc * 3 + 2]);
                }
#pragma unroll
                for (int off = 16; off; off >>= 1) {
                    p0 += __shfl_xor_sync(0xFFFFFFFFu, p0, off);
                    p1 += __shfl_xor_sync(0xFFFFFFFFu, p1, off);
                    p2 += __shfl_xor_sync(0xFFFFFFFFu, p2, off);
                }
                int n = n0 + r;
                if (lane == 0 && n < N_NODES) {
                    out_pos[n * 3 + 0] = p0 + __ldg(&bv2[0]);
                    out_pos[n * 3 + 1] = p1 + __ldg(&bv2[1]);
                    out_pos[n * 3 + 2] = p2 + __ldg(&bv2[2]);
                }
            }
        } else {
            __half* outp = (m == 1) ? g_ph : g_qh;
            const float* bias = (m == 1) ? be1 : nullptr;
            for (int j = tid; j < 64 * 128; j += 128) {
                int r = j >> 7, cc = j & 127;
                float v = sC[r][cc] + (bias ? __ldg(&bias[cc]) : 0.f);
                outp[(size_t)(n0 + r) * HID + cc] = __float2half_rn(v);
            }
        }
    }
}

// ---------------- fused GAT + edge MLP: warp per dst node ----------------
__global__ void k_gatedge(const float* __restrict__ att_src, const float* __restrict__ att_dst,
                          const float* __restrict__ bg, const float* __restrict__ we2,
                          const float* __restrict__ be2,
                          float* __restrict__ out_ew, float* __restrict__ out_conn) {
    int gt = blockIdx.x * blockDim.x + threadIdx.x;
    int n = gt >> 5;
    if (n >= N_NODES) return;
    int lane = gt & 31;
    int sub = lane >> 4, l = lane & 15;
    unsigned halfmask = sub ? 0xFFFF0000u : 0x0000FFFFu;

    uint4 qraw = *(const uint4*)(g_qh + (size_t)n * HID + l * 8);   // 8 halves
    float w[8];
    {
        float4 wa = *(const float4*)&we2[l * 8];
        float4 wb = *(const float4*)&we2[l * 8 + 4];
        w[0] = wa.x; w[1] = wa.y; w[2] = wa.z; w[3] = wa.w;
        w[4] = wb.x; w[5] = wb.y; w[6] = wb.z; w[7] = wb.w;
    }
    float qf[8];
    {
        const unsigned* qr = (const unsigned*)&qraw;
#pragma unroll
        for (int j = 0; j < 4; j++) {
            float2 f = __half22float2(*(const __half2*)&qr[j]);
            qf[j * 2] = f.x; qf[j * 2 + 1] = f.y;
        }
    }
    float as_ = __ldg(att_src), ad = __ldg(att_dst);
    float hgd = g_hg[n] * ad;
    float be2v = __ldg(be2);
    int beg = g_off[n], end = g_off[n + 1];

    float mx = -3.4e38f, ssum = 0.f, aacc = 0.f;
    for (int i = beg + sub; i < end; i += 2) {
        int s = g_csr_src[i];
        uint4 praw = *(const uint4*)(g_ph + (size_t)s * HID + l * 8);
        const unsigned* pr = (const unsigned*)&praw;
        float acc = 0.f;
#pragma unroll
        for (int j = 0; j < 4; j++) {
            float2 pf = __half22float2(*(const __half2*)&pr[j]);
            acc += fmaxf(pf.x + qf[j * 2], 0.f) * w[j * 2]
                 + fmaxf(pf.y + qf[j * 2 + 1], 0.f) * w[j * 2 + 1];
        }
#pragma unroll
        for (int off = 8; off; off >>= 1)
            acc += __shfl_down_sync(halfmask, acc, off, 16);
        if (l == 0) {
            int e = g_csr_eid[i];
            out_conn[e] = 1.f / (1.f + __expf(-(acc + be2v)));
            float hs = g_hg[s];
            float v = hs * as_ + hgd;
            v = v > 0.f ? v : 0.2f * v;
            float nm = fmaxf(mx, v);
            float e1 = __expf(mx - nm);
            float e2 = __expf(v - nm);
            ssum = ssum * e1 + e2;
            aacc = aacc * e1 + e2 * hs;
            mx = nm;
        }
    }
    float om = __shfl_sync(0xFFFFFFFFu, mx, 16);
    float os = __shfl_sync(0xFFFFFFFFu, ssum, 16);
    float oa = __shfl_sync(0xFFFFFFFFu, aacc, 16);
    if (lane == 0) {
        float nm = fmaxf(mx, om);
        float e1 = __expf(mx - nm);
        float e2 = __expf(om - nm);
        float s = ssum * e1 + os * e2;
        float a = aacc * e1 + oa * e2;
        out_ew[n] = a / (s + 1e-16f) + __ldg(bg);
    }
}

// ---------------- launcher ----------------
extern "C" void kernel_launch(void* const* d_in, const int* in_sizes, int n_in,
                              void* d_out, int out_size) {
    (void)in_sizes; (void)n_in; (void)out_size;
    const float* x  = (const float*)d_in[0];
    const void*  ei = d_in[1];
    const float* w1l = (const float*)d_in[3];
    const float* b1  = (const float*)d_in[4];
    const float* w1r = (const float*)d_in[5];
    const float* w2l = (const float*)d_in[6];
    const float* b2  = (const float*)d_in[7];
    const float* w2r = (const float*)d_in[8];
    const float* wg  = (const float*)d_in[9];
    const float* att_src = (const float*)d_in[10];
    const float* att_dst = (const float*)d_in[11];
    const float* bg  = (const float*)d_in[12];
    const float* wv1 = (const float*)d_in[13];
    const float* bv1 = (const float*)d_in[14];
    const float* wv2 = (const float*)d_in[15];
    const float* bv2 = (const float*)d_in[16];
    const float* we1 = (const float*)d_in[17];
    const float* be1 = (const float*)d_in[18];
    const float* we2 = (const float*)d_in[19];
    const float* be2 = (const float*)d_in[20];

    float* out      = (float*)d_out;
    float* out_pos  = out;                         // [N,3]
    float* out_conn = out + N_NODES * 3;           // [E,1]
    float* out_ew   = out + N_NODES * 3 + N_EDGES; // [N,1]

    cudaFuncSetAttribute(k_gemm_all, cudaFuncAttributeMaxDynamicSharedMemorySize, GEMM_SMEM);

    const int T = 256;
    k_setup<<<512, T>>>(x, (const int*)ei, w2l, w2r, wv1, we1);
    k_convert<<<2048, T>>>(ei);

    // CSR build
    k_scan1<<<NB, CHUNK>>>();
    k_scan2<<<1, 1024>>>();
    k_scan3<<<NB, CHUNK>>>();
    k_fill<<<(N_EDGES + T - 1) / T, T>>>(ei);

    // SAGE-1 fused
    k_sage1<<<(N_NODES + 7) / 8, 256>>>(w1l, b1, w1r);

    // SAGE-2 + t/p/q + positions + hg, all in one kernel
    k_gemm_all<<<NPAD / 64, 128, GEMM_SMEM>>>(b2, wg, bv1, be1, wv2, bv2, out_pos);

    // GAT + edge MLP fused
    k_gatedge<<<(N_NODES * 32 + T - 1) / T, T>>>(att_src, att_dst, bg, we2, be2,
                                                 out_ew, out_conn);
}

// round 14
// speedup vs baseline: 1.1898x; 1.1898x over previous
#include <cuda_runtime.h>
#include <cuda_fp16.h>
#include <mma.h>
#include <math.h>

using namespace nvcuda;

#define N_NODES 100000
#define N_EDGES 1600000
#define HID     128
#define CHUNK   128
#define NB      ((N_NODES + CHUNK - 1) / CHUNK)   // 782
#define NPAD    100352                            // 1568 * 64
#define GEMM_SMEM 52224                           // 17408 (A) + 34816 (B/C)

// ---------------- scratch (static device globals; no runtime allocation) ----------------
static __device__ int      g_is64;
static __device__ int      g_deg [N_NODES];
static __device__ int      g_part[NB];
static __device__ int      g_partoff[NB];
static __device__ int      g_off [N_NODES + 1];
static __device__ int      g_cur [N_NODES];
static __device__ int      g_csr_src[N_EDGES];
static __device__ int      g_csr_eid[N_EDGES];
static __device__ __align__(16) float  g_x8 [N_NODES * 8];    // fp32 (self term)
static __device__ __align__(16) __half g_x8h[N_NODES * 8];    // fp16 (gathered)
static __device__ __align__(16) __half g_h1h[NPAD * HID];     // fp16 (pad rows stay zero)
static __device__ __align__(16) __half g_h2h[NPAD * HID];     // fp16
static __device__ __align__(16) __half g_ph [NPAD * HID];     // fp16 (gathered)
static __device__ __align__(16) __half g_qh [NPAD * HID];     // fp16
static __device__ float    g_hg [N_NODES];
// fp16 weights: w2cat [256][128] (rows 0-127 w2l, 128-255 w2r); w_h[m] [128][128] [k][c]
static __device__ __align__(16) __half g_w2cat_h[256 * HID];
static __device__ __align__(16) __half g_w_h[3][HID * HID];

// ---------------- setup: dtype detect + deg clear + x8 + fp16 weights ----------------
__global__ void k_setup(const float* __restrict__ x, const int* __restrict__ ei32,
                        const float* __restrict__ w2l, const float* __restrict__ w2r,
                        const float* __restrict__ wv1, const float* __restrict__ we1) {
    int idx = blockIdx.x * blockDim.x + threadIdx.x;
    int stride = gridDim.x * blockDim.x;
    if (idx == 0) {
        int nz = 0;
        for (int j = 0; j < 256; j++) nz |= ei32[2 * j + 1];
        g_is64 = (nz == 0) ? 1 : 0;   // int64 values < 2^31 -> odd words all zero
    }
    for (int n = idx; n < N_NODES; n += stride) {
        g_deg[n] = 0;
        const float* xr = x + (size_t)n * 7;
        float4 a, b;
        a.x = xr[0]; a.y = xr[1]; a.z = xr[2]; a.w = xr[3];
        b.x = xr[4]; b.y = xr[5]; b.z = xr[6]; b.w = 0.f;
        ((float4*)g_x8)[(size_t)n * 2 + 0] = a;
        ((float4*)g_x8)[(size_t)n * 2 + 1] = b;
        __half2* hp = (__half2*)(g_x8h + (size_t)n * 8);
        hp[0] = __floats2half2_rn(a.x, a.y);
        hp[1] = __floats2half2_rn(a.z, a.w);
        hp[2] = __floats2half2_rn(b.x, b.y);
        hp[3] = __floats2half2_rn(b.z, b.w);
    }
    for (int i = idx; i < 256 * HID; i += stride) {
        int k = i >> 7, c = i & 127;
        float v = (k < 128) ? w2l[k * HID + c] : w2r[(k - 128) * HID + c];
        g_w2cat_h[i] = __float2half_rn(v);
    }
    for (int j = idx; j < 3 * HID * HID; j += stride) {
        int m = j >> 14;
        int e = j & 16383;
        float v = (m == 0) ? wv1[e] : (m == 1) ? we1[e] : we1[16384 + e];
        g_w_h[m][e] = __float2half_rn(v);
    }
}

// degree histogram straight from edge_index
__global__ void k_convert(const void* __restrict__ ei) {
    int i = blockIdx.x * blockDim.x + threadIdx.x;
    int stride = gridDim.x * blockDim.x;
    const int is64 = g_is64;
    for (int e = i; e < N_EDGES; e += stride) {
        int d;
        if (is64) d = (int)((const long long*)ei)[N_EDGES + e];
        else      d = ((const int*)ei)[N_EDGES + e];
        d = min(max(d, 0), N_NODES - 1);
        atomicAdd(&g_deg[d], 1);
    }
}

// ---------------- CSR build ----------------
__global__ void k_scan1() {
    __shared__ int sh[CHUNK];
    int b = blockIdx.x, tid = threadIdx.x;
    int i = b * CHUNK + tid;
    sh[tid] = (i < N_NODES) ? g_deg[i] : 0;
    __syncthreads();
    for (int off = 64; off; off >>= 1) {
        if (tid < off) sh[tid] += sh[tid + off];
        __syncthreads();
    }
    if (tid == 0) g_part[b] = sh[0];
}

__global__ void k_scan2() {
    __shared__ int sh[1024];
    int tid = threadIdx.x;
    int v = (tid < NB) ? g_part[tid] : 0;
    sh[tid] = v;
    __syncthreads();
    for (int off = 1; off < 1024; off <<= 1) {
        int add = (tid >= off) ? sh[tid - off] : 0;
        __syncthreads();
        sh[tid] += add;
        __syncthreads();
    }
    if (tid < NB) g_partoff[tid] = sh[tid] - v;
    if (tid == 1023) g_off[N_NODES] = sh[tid];
}

__global__ void k_scan3() {
    __shared__ int sh[CHUNK];
    int b = blockIdx.x, tid = threadIdx.x;
    int i = b * CHUNK + tid;
    int v = (i < N_NODES) ? g_deg[i] : 0;
    sh[tid] = v;
    __syncthreads();
    for (int off = 1; off < CHUNK; off <<= 1) {
        int add = (tid >= off) ? sh[tid - off] : 0;
        __syncthreads();
        sh[tid] += add;
        __syncthreads();
    }
    if (i < N_NODES) {
        int excl = g_partoff[b] + sh[tid] - v;
        g_off[i] = excl;
        g_cur[i] = excl;
    }
}

// fill CSR, converting directly from edge_index
__global__ void k_fill(const void* __restrict__ ei) {
    int e = blockIdx.x * blockDim.x + threadIdx.x;
    if (e >= N_EDGES) return;
    const int is64 = g_is64;
    int s, d;
    if (is64) {
        const long long* p = (const long long*)ei;
        s = (int)p[e]; d = (int)p[N_EDGES + e];
    } else {
        const int* p = (const int*)ei;
        s = p[e]; d = p[N_EDGES + e];
    }
    s = min(max(s, 0), N_NODES - 1);
    d = min(max(d, 0), N_NODES - 1);
    int pos = atomicAdd(&g_cur[d], 1);
    g_csr_src[pos] = s;
    g_csr_eid[pos] = e;
}

// ---------------- fused SAGE-1: aggregate (fp16 gather) + linear + relu -> h1h ---------
__global__ void k_sage1(const float* __restrict__ w1l, const float* __restrict__ b1,
                        const float* __restrict__ w1r) {
    __shared__ float s_wl[7][HID], s_wr[7][HID], s_b[HID];
    int tid = threadIdx.x;
    for (int j = tid; j < 7 * HID; j += 256) {
        s_wl[j >> 7][j & 127] = w1l[j];
        s_wr[j >> 7][j & 127] = w1r[j];
    }
    if (tid < HID) s_b[tid] = b1[tid];
    __syncthreads();
    int wid = tid >> 5, lane = tid & 31;
    int n = blockIdx.x * 8 + wid;
    if (n >= N_NODES) return;
    int beg = g_off[n], end = g_off[n + 1];
    float a0 = 0.f, a1 = 0.f, a2 = 0.f, a3 = 0.f, a4 = 0.f, a5 = 0.f, a6 = 0.f;
    for (int i = beg + lane; i < end; i += 32) {
        int s = g_csr_src[i];
        uint4 raw = *(const uint4*)(g_x8h + (size_t)s * 8);
        float2 f0 = __half22float2(*(__half2*)&raw.x);
        float2 f1 = __half22float2(*(__half2*)&raw.y);
        float2 f2 = __half22float2(*(__half2*)&raw.z);
        float2 f3 = __half22float2(*(__half2*)&raw.w);
        a0 += f0.x; a1 += f0.y; a2 += f1.x; a3 += f1.y;
        a4 += f2.x; a5 += f2.y; a6 += f3.x;
    }
#pragma unroll
    for (int off = 16; off; off >>= 1) {
        a0 += __shfl_xor_sync(0xFFFFFFFFu, a0, off);
        a1 += __shfl_xor_sync(0xFFFFFFFFu, a1, off);
        a2 += __shfl_xor_sync(0xFFFFFFFFu, a2, off);
        a3 += __shfl_xor_sync(0xFFFFFFFFu, a3, off);
        a4 += __shfl_xor_sync(0xFFFFFFFFu, a4, off);
        a5 += __shfl_xor_sync(0xFFFFFFFFu, a5, off);
        a6 += __shfl_xor_sync(0xFFFFFFFFu, a6, off);
    }
    float inv = 1.f / fmaxf((float)(end - beg), 1.f);
    float m[7] = {a0 * inv, a1 * inv, a2 * inv, a3 * inv, a4 * inv, a5 * inv, a6 * inv};
    const float4* xp = (const float4*)(g_x8 + (size_t)n * 8);
    float4 u = xp[0];
    float4 w = xp[1];
    float xn[7] = {u.x, u.y, u.z, u.w, w.x, w.y, w.z};
#pragma unroll
    for (int j = 0; j < 4; j++) {
        int c = lane + 32 * j;
        float acc = s_b[c];
#pragma unroll
        for (int k = 0; k < 7; k++)
            acc += m[k] * s_wl[k][c] + xn[k] * s_wr[k][c];
        g_h1h[(size_t)n * HID + c] = __float2half_rn(fmaxf(acc, 0.f));
    }
}

// ---------------- SAGE-2: fused mean-gather + wmma GEMM (K=256) + hg epilogue ----------
// warp tiling: 2x2 warp grid, each warp owns a 32x64 output tile (fewer LDSM loads)
__global__ void __launch_bounds__(128) k_node2(const float* __restrict__ b2,
                                               const float* __restrict__ wg) {
    extern __shared__ __align__(16) char smem[];
    __half (*sA)[136] = (__half(*)[136])smem;               // 64 x 136
    __half (*sB)[136] = (__half(*)[136])(smem + 17408);     // 128 x 136
    float  (*sC)[136] = (float (*)[136])(smem + 17408);     // reuse
    int tid = threadIdx.x;
    int warp = tid >> 5, lane = tid & 31;
    int wr = warp >> 1, wc = warp & 1;                      // 2x2 warp grid
    int n0 = blockIdx.x * 64;

    // ---- prologue: gather mean(h1h[neighbors]) into sA (one warp per node, unroll 4)
    for (int r = warp; r < 64; r += 4) {
        int n = n0 + r;
        float4 acc = {0.f, 0.f, 0.f, 0.f};
        float inv = 0.f;
        if (n < N_NODES) {
            int beg = g_off[n], end = g_off[n + 1];
            int i = beg;
            for (; i + 4 <= end; i += 4) {
                int s0 = g_csr_src[i], s1 = g_csr_src[i + 1];
                int s2 = g_csr_src[i + 2], s3 = g_csr_src[i + 3];
                uint2 r0 = *(const uint2*)(g_h1h + (size_t)s0 * HID + lane * 4);
                uint2 r1 = *(const uint2*)(g_h1h + (size_t)s1 * HID + lane * 4);
                uint2 r2 = *(const uint2*)(g_h1h + (size_t)s2 * HID + lane * 4);
                uint2 r3 = *(const uint2*)(g_h1h + (size_t)s3 * HID + lane * 4);
                float2 f;
                f = __half22float2(*(__half2*)&r0.x); acc.x += f.x; acc.y += f.y;
                f = __half22float2(*(__half2*)&r0.y); acc.z += f.x; acc.w += f.y;
                f = __half22float2(*(__half2*)&r1.x); acc.x += f.x; acc.y += f.y;
                f = __half22float2(*(__half2*)&r1.y); acc.z += f.x; acc.w += f.y;
                f = __half22float2(*(__half2*)&r2.x); acc.x += f.x; acc.y += f.y;
                f = __half22float2(*(__half2*)&r2.y); acc.z += f.x; acc.w += f.y;
                f = __half22float2(*(__half2*)&r3.x); acc.x += f.x; acc.y += f.y;
                f = __half22float2(*(__half2*)&r3.y); acc.z += f.x; acc.w += f.y;
            }
            for (; i < end; i++) {
                int s = g_csr_src[i];
                uint2 r0 = *(const uint2*)(g_h1h + (size_t)s * HID + lane * 4);
                float2 f;
                f = __half22float2(*(__half2*)&r0.x); acc.x += f.x; acc.y += f.y;
                f = __half22float2(*(__half2*)&r0.y); acc.z += f.x; acc.w += f.y;
            }
            inv = 1.f / fmaxf((float)(end - beg), 1.f);
        }
        __half2 h01 = __floats2half2_rn(acc.x * inv, acc.y * inv);
        __half2 h23 = __floats2half2_rn(acc.z * inv, acc.w * inv);
        uint2 packed;
        packed.x = *(unsigned*)&h01;
        packed.y = *(unsigned*)&h23;
        *(uint2*)&sA[r][lane * 4] = packed;
    }

    wmma::fragment<wmma::accumulator, 16, 16, 16, float> c[2][4];
#pragma unroll
    for (int i = 0; i < 2; i++)
#pragma unroll
        for (int j = 0; j < 4; j++) wmma::fill_fragment(c[i][j], 0.f);
    wmma::fragment<wmma::matrix_a, 16, 16, 16, __half, wmma::row_major> a0, a1;
    wmma::fragment<wmma::matrix_b, 16, 16, 16, __half, wmma::row_major> b;

    // ---- kh = 0: A = mean (sA), B = w2l rows
    {
        const uint4* wsrc = (const uint4*)g_w2cat_h;
        for (int j = tid; j < 128 * 16; j += 128) {
            int r = j >> 4, c4 = j & 15;
            ((uint4*)&sB[r][0])[c4] = wsrc[(size_t)r * 16 + c4];
        }
        __syncthreads();
#pragma unroll
        for (int kt = 0; kt < 8; kt++) {
            wmma::load_matrix_sync(a0, &sA[wr * 32][kt * 16], 136);
            wmma::load_matrix_sync(a1, &sA[wr * 32 + 16][kt * 16], 136);
#pragma unroll
            for (int nt = 0; nt < 4; nt++) {
                wmma::load_matrix_sync(b, &sB[kt * 16][wc * 64 + nt * 16], 136);
                wmma::mma_sync(c[0][nt], a0, b, c[0][nt]);
                wmma::mma_sync(c[1][nt], a1, b, c[1][nt]);
            }
        }
        __syncthreads();
    }
    // ---- kh = 1: A = h1h rows, B = w2r rows
    {
        const uint4* asrc = (const uint4*)g_h1h;
        for (int j = tid; j < 64 * 16; j += 128) {
            int r = j >> 4, c4 = j & 15;
            ((uint4*)&sA[r][0])[c4] = asrc[(size_t)(n0 + r) * 16 + c4];
        }
        const uint4* wsrc = (const uint4*)g_w2cat_h;
        for (int j = tid; j < 128 * 16; j += 128) {
            int r = j >> 4, c4 = j & 15;
            ((uint4*)&sB[r][0])[c4] = wsrc[(size_t)(128 + r) * 16 + c4];
        }
        __syncthreads();
#pragma unroll
        for (int kt = 0; kt < 8; kt++) {
            wmma::load_matrix_sync(a0, &sA[wr * 32][kt * 16], 136);
            wmma::load_matrix_sync(a1, &sA[wr * 32 + 16][kt * 16], 136);
#pragma unroll
            for (int nt = 0; nt < 4; nt++) {
                wmma::load_matrix_sync(b, &sB[kt * 16][wc * 64 + nt * 16], 136);
                wmma::mma_sync(c[0][nt], a0, b, c[0][nt]);
                wmma::mma_sync(c[1][nt], a1, b, c[1][nt]);
            }
        }
        __syncthreads();
    }
#pragma unroll
    for (int i = 0; i < 2; i++)
#pragma unroll
        for (int nt = 0; nt < 4; nt++)
            wmma::store_matrix_sync(&sC[wr * 32 + i * 16][wc * 64 + nt * 16],
                                    c[i][nt], 136, wmma::mem_row_major);
    __syncthreads();
    // ---- epilogue: h2h (fp16) + hg = (sC + b2) . wg
    for (int j = tid; j < 64 * 128; j += 128) {
        int r = j >> 7, cc = j & 127;
        float v = sC[r][cc] + __ldg(&b2[cc]);
        g_h2h[(size_t)(n0 + r) * HID + cc] = __float2half_rn(v);
    }
    for (int r = warp; r < 64; r += 4) {
        float part = 0.f;
#pragma unroll
        for (int j = 0; j < 4; j++) {
            int cc = lane + 32 * j;
            part += (sC[r][cc] + __ldg(&b2[cc])) * __ldg(&wg[cc]);
        }
#pragma unroll
        for (int off = 16; off; off >>= 1)
            part += __shfl_xor_sync(0xFFFFFFFFu, part, off);
        if (lane == 0 && n0 + r < N_NODES) g_hg[n0 + r] = part;
    }
}

// ---------------- t/p/q: wmma GEMMs, 2x2 warp tiling; positions fused ----------------
__global__ void __launch_bounds__(128) k_tpq(const float* __restrict__ bv1,
                                             const float* __restrict__ be1,
                                             const float* __restrict__ wv2,
                                             const float* __restrict__ bv2,
                                             float* __restrict__ out_pos) {
    extern __shared__ __align__(16) char smem[];
    __half (*sA)[136] = (__half(*)[136])smem;               // 64 x 136
    __half (*sB)[136] = (__half(*)[136])(smem + 17408);     // 128 x 136
    float  (*sC)[136] = (float (*)[136])(smem + 17408);     // reuse
    int tid = threadIdx.x;
    int warp = tid >> 5, lane = tid & 31;
    int wr = warp >> 1, wc = warp & 1;
    int n0 = blockIdx.x * 64;

    const uint4* asrc = (const uint4*)g_h2h;
    for (int j = tid; j < 64 * 16; j += 128) {
        int r = j >> 4, c4 = j & 15;
        ((uint4*)&sA[r][0])[c4] = asrc[(size_t)(n0 + r) * 16 + c4];
    }
    __syncthreads();

    wmma::fragment<wmma::matrix_a, 16, 16, 16, __half, wmma::row_major> a0, a1;
    wmma::fragment<wmma::matrix_b, 16, 16, 16, __half, wmma::row_major> b;

#pragma unroll 1
    for (int m = 0; m < 3; m++) {
        const uint4* wsrc = (const uint4*)g_w_h[m];
        for (int j = tid; j < 128 * 16; j += 128) {
            int r = j >> 4, c4 = j & 15;
            ((uint4*)&sB[r][0])[c4] = wsrc[(size_t)r * 16 + c4];
        }
        __syncthreads();
        wmma::fragment<wmma::accumulator, 16, 16, 16, float> c[2][4];
#pragma unroll
        for (int i = 0; i < 2; i++)
#pragma unroll
            for (int j = 0; j < 4; j++) wmma::fill_fragment(c[i][j], 0.f);
#pragma unroll
        for (int kt = 0; kt < 8; kt++) {
            wmma::load_matrix_sync(a0, &sA[wr * 32][kt * 16], 136);
            wmma::load_matrix_sync(a1, &sA[wr * 32 + 16][kt * 16], 136);
#pragma unroll
            for (int nt = 0; nt < 4; nt++) {
                wmma::load_matrix_sync(b, &sB[kt * 16][wc * 64 + nt * 16], 136);
                wmma::mma_sync(c[0][nt], a0, b, c[0][nt]);
                wmma::mma_sync(c[1][nt], a1, b, c[1][nt]);
            }
        }
        __syncthreads();
#pragma unroll
        for (int i = 0; i < 2; i++)
#pragma unroll
            for (int nt = 0; nt < 4; nt++)
                wmma::store_matrix_sync(&sC[wr * 32 + i * 16][wc * 64 + nt * 16],
                                        c[i][nt], 136, wmma::mem_row_major);
        __syncthreads();
        if (m == 0) {
            // positions: pos = relu(sC + bv1) . wv2 + bv2   (t never materialized)
            for (int r = warp; r < 64; r += 4) {
                float p0 = 0.f, p1 = 0.f, p2 = 0.f;
#pragma unroll
                for (int j = 0; j < 4; j++) {
                    int cc = lane + 32 * j;
                    float tv = fmaxf(sC[r][cc] + __ldg(&bv1[cc]), 0.f);
                    p0 += tv * __ldg(&wv2[cc * 3 + 0]);
                    p1 += tv * __ldg(&wv2[cc * 3 + 1]);
                    p2 += tv * __ldg(&wv2[cc * 3 + 2]);
                }
#pragma unroll
                for (int off = 16; off; off >>= 1) {
                    p0 += __shfl_xor_sync(0xFFFFFFFFu, p0, off);
                    p1 += __shfl_xor_sync(0xFFFFFFFFu, p1, off);
                    p2 += __shfl_xor_sync(0xFFFFFFFFu, p2, off);
                }
                int n = n0 + r;
                if (lane == 0 && n < N_NODES) {
                    out_pos[n * 3 + 0] = p0 + __ldg(&bv2[0]);
                    out_pos[n * 3 + 1] = p1 + __ldg(&bv2[1]);
                    out_pos[n * 3 + 2] = p2 + __ldg(&bv2[2]);
                }
            }
        } else {
            __half* outp = (m == 1) ? g_ph : g_qh;
            const float* bias = (m == 1) ? be1 : nullptr;
            for (int j = tid; j < 64 * 128; j += 128) {
                int r = j >> 7, cc = j & 127;
                float v = sC[r][cc] + (bias ? __ldg(&bias[cc]) : 0.f);
                outp[(size_t)(n0 + r) * HID + cc] = __float2half_rn(v);
            }
        }
        __syncthreads();
    }
}

// ---------------- fused GAT + edge MLP: warp per dst node ----------------
__global__ void k_gatedge(const float* __restrict__ att_src, const float* __restrict__ att_dst,
                          const float* __restrict__ bg, const float* __restrict__ we2,
                          const float* __restrict__ be2,
                          float* __restrict__ out_ew, float* __restrict__ out_conn) {
    int gt = blockIdx.x * blockDim.x + threadIdx.x;
    int n = gt >> 5;
    if (n >= N_NODES) return;
    int lane = gt & 31;
    int sub = lane >> 4, l = lane & 15;
    unsigned halfmask = sub ? 0xFFFF0000u : 0x0000FFFFu;

    uint4 qraw = *(const uint4*)(g_qh + (size_t)n * HID + l * 8);   // 8 halves
    float w[8];
    {
        float4 wa = *(const float4*)&we2[l * 8];
        float4 wb = *(const float4*)&we2[l * 8 + 4];
        w[0] = wa.x; w[1] = wa.y; w[2] = wa.z; w[3] = wa.w;
        w[4] = wb.x; w[5] = wb.y; w[6] = wb.z; w[7] = wb.w;
    }
    float qf[8];
    {
        const unsigned* qr = (const unsigned*)&qraw;
#pragma unroll
        for (int j = 0; j < 4; j++) {
            float2 f = __half22float2(*(const __half2*)&qr[j]);
            qf[j * 2] = f.x; qf[j * 2 + 1] = f.y;
        }
    }
    float as_ = __ldg(att_src), ad = __ldg(att_dst);
    float hgd = g_hg[n] * ad;
    float be2v = __ldg(be2);
    int beg = g_off[n], end = g_off[n + 1];

    float mx = -3.4e38f, ssum = 0.f, aacc = 0.f;
    for (int i = beg + sub; i < end; i += 2) {
        int s = g_csr_src[i];
        uint4 praw = *(const uint4*)(g_ph + (size_t)s * HID + l * 8);
        const unsigned* pr = (const unsigned*)&praw;
        float acc = 0.f;
#pragma unroll
        for (int j = 0; j < 4; j++) {
            float2 pf = __half22float2(*(const __half2*)&pr[j]);
            acc += fmaxf(pf.x + qf[j * 2], 0.f) * w[j * 2]
                 + fmaxf(pf.y + qf[j * 2 + 1], 0.f) * w[j * 2 + 1];
        }
#pragma unroll
        for (int off = 8; off; off >>= 1)
            acc += __shfl_down_sync(halfmask, acc, off, 16);
        if (l == 0) {
            int e = g_csr_eid[i];
            out_conn[e] = 1.f / (1.f + __expf(-(acc + be2v)));
            float hs = g_hg[s];
            float v = hs * as_ + hgd;
            v = v > 0.f ? v : 0.2f * v;
            float nm = fmaxf(mx, v);
            float e1 = __expf(mx - nm);
            float e2 = __expf(v - nm);
            ssum = ssum * e1 + e2;
            aacc = aacc * e1 + e2 * hs;
            mx = nm;
        }
    }
    float om = __shfl_sync(0xFFFFFFFFu, mx, 16);
    float os = __shfl_sync(0xFFFFFFFFu, ssum, 16);
    float oa = __shfl_sync(0xFFFFFFFFu, aacc, 16);
    if (lane == 0) {
        float nm = fmaxf(mx, om);
        float e1 = __expf(mx - nm);
        float e2 = __expf(om - nm);
        float s = ssum * e1 + os * e2;
        float a = aacc * e1 + oa * e2;
        out_ew[n] = a / (s + 1e-16f) + __ldg(bg);
    }
}

// ---------------- launcher ----------------
extern "C" void kernel_launch(void* const* d_in, const int* in_sizes, int n_in,
                              void* d_out, int out_size) {
    (void)in_sizes; (void)n_in; (void)out_size;
    const float* x  = (const float*)d_in[0];
    const void*  ei = d_in[1];
    const float* w1l = (const float*)d_in[3];
    const float* b1  = (const float*)d_in[4];
    const float* w1r = (const float*)d_in[5];
    const float* w2l = (const float*)d_in[6];
    const float* b2  = (const float*)d_in[7];
    const float* w2r = (const float*)d_in[8];
    const float* wg  = (const float*)d_in[9];
    const float* att_src = (const float*)d_in[10];
    const float* att_dst = (const float*)d_in[11];
    const float* bg  = (const float*)d_in[12];
    const float* wv1 = (const float*)d_in[13];
    const float* bv1 = (const float*)d_in[14];
    const float* wv2 = (const float*)d_in[15];
    const float* bv2 = (const float*)d_in[16];
    const float* we1 = (const float*)d_in[17];
    const float* be1 = (const float*)d_in[18];
    const float* we2 = (const float*)d_in[19];
    const float* be2 = (const float*)d_in[20];

    float* out      = (float*)d_out;
    float* out_pos  = out;                         // [N,3]
    float* out_conn = out + N_NODES * 3;           // [E,1]
    float* out_ew   = out + N_NODES * 3 + N_EDGES; // [N,1]

    cudaFuncSetAttribute(k_node2, cudaFuncAttributeMaxDynamicSharedMemorySize, GEMM_SMEM);
    cudaFuncSetAttribute(k_tpq,   cudaFuncAttributeMaxDynamicSharedMemorySize, GEMM_SMEM);

    const int T = 256;
    k_setup<<<512, T>>>(x, (const int*)ei, w2l, w2r, wv1, we1);
    k_convert<<<2048, T>>>(ei);

    // CSR build
    k_scan1<<<NB, CHUNK>>>();
    k_scan2<<<1, 1024>>>();
    k_scan3<<<NB, CHUNK>>>();
    k_fill<<<(N_EDGES + T - 1) / T, T>>>(ei);

    // SAGE-1 fused
    k_sage1<<<(N_NODES + 7) / 8, 256>>>(w1l, b1, w1r);

    // SAGE-2 (mean gather + GEMM + hg fused)
    k_node2<<<NPAD / 64, 128, GEMM_SMEM>>>(b2, wg);

    // t/p/q GEMMs (positions fused into epilogue)
    k_tpq<<<NPAD / 64, 128, GEMM_SMEM>>>(bv1, be1, wv2, bv2, out_pos);

    // GAT + edge MLP fused
    k_gatedge<<<(N_NODES * 32 + T - 1) / T, T>>>(att_src, att_dst, bg, we2, be2,
                                                 out_ew, out_conn);
}

// round 15
// speedup vs baseline: 1.2455x; 1.0469x over previous
#include <cuda_runtime.h>
#include <cuda_fp16.h>
#include <mma.h>
#include <math.h>

using namespace nvcuda;

#define N_NODES 100000
#define N_EDGES 1600000
#define HID     128
#define CHUNK   128
#define NB      ((N_NODES + CHUNK - 1) / CHUNK)   // 782
#define NPAD    100352                            // 1568 * 64
#define GEMM_SMEM 52224                           // 17408 (A) + 34816 (B/C)

// ---------------- scratch (static device globals; no runtime allocation) ----------------
static __device__ int      g_is64;
static __device__ int      g_deg [N_NODES];
static __device__ int      g_part[NB];
static __device__ int      g_partoff[NB];
static __device__ int      g_off [N_NODES + 1];
static __device__ int      g_cur [N_NODES];
static __device__ int      g_csr_src[N_EDGES];
static __device__ int      g_csr_eid[N_EDGES];
static __device__ __align__(16) float  g_x8 [N_NODES * 8];    // fp32 (self term)
static __device__ __align__(16) __half g_x8h[N_NODES * 8];    // fp16 (gathered)
static __device__ __align__(16) __half g_h1h[NPAD * HID];     // fp16 (pad rows stay zero)
static __device__ __align__(16) __half g_h2h[NPAD * HID];     // fp16
static __device__ __align__(16) __half g_ph [NPAD * HID];     // fp16 (gathered)
static __device__ __align__(16) __half g_qh [NPAD * HID];     // fp16
static __device__ float    g_hg [N_NODES];
// fp16 weights: w2cat [256][128] (rows 0-127 w2l, 128-255 w2r); w_h[m] [128][128] [k][c]
static __device__ __align__(16) __half g_w2cat_h[256 * HID];
static __device__ __align__(16) __half g_w_h[3][HID * HID];

// ---------------- setup: dtype detect + deg clear + x8 + fp16 weights ----------------
__global__ void k_setup(const float* __restrict__ x, const int* __restrict__ ei32,
                        const float* __restrict__ w2l, const float* __restrict__ w2r,
                        const float* __restrict__ wv1, const float* __restrict__ we1) {
    int idx = blockIdx.x * blockDim.x + threadIdx.x;
    int stride = gridDim.x * blockDim.x;
    if (idx == 0) {
        int nz = 0;
        for (int j = 0; j < 256; j++) nz |= ei32[2 * j + 1];
        g_is64 = (nz == 0) ? 1 : 0;   // int64 values < 2^31 -> odd words all zero
    }
    for (int n = idx; n < N_NODES; n += stride) {
        g_deg[n] = 0;
        const float* xr = x + (size_t)n * 7;
        float4 a, b;
        a.x = xr[0]; a.y = xr[1]; a.z = xr[2]; a.w = xr[3];
        b.x = xr[4]; b.y = xr[5]; b.z = xr[6]; b.w = 0.f;
        ((float4*)g_x8)[(size_t)n * 2 + 0] = a;
        ((float4*)g_x8)[(size_t)n * 2 + 1] = b;
        __half2* hp = (__half2*)(g_x8h + (size_t)n * 8);
        hp[0] = __floats2half2_rn(a.x, a.y);
        hp[1] = __floats2half2_rn(a.z, a.w);
        hp[2] = __floats2half2_rn(b.x, b.y);
        hp[3] = __floats2half2_rn(b.z, b.w);
    }
    for (int i = idx; i < 256 * HID; i += stride) {
        int k = i >> 7, c = i & 127;
        float v = (k < 128) ? w2l[k * HID + c] : w2r[(k - 128) * HID + c];
        g_w2cat_h[i] = __float2half_rn(v);
    }
    for (int j = idx; j < 3 * HID * HID; j += stride) {
        int m = j >> 14;
        int e = j & 16383;
        float v = (m == 0) ? wv1[e] : (m == 1) ? we1[e] : we1[16384 + e];
        g_w_h[m][e] = __float2half_rn(v);
    }
}

// degree histogram straight from edge_index
__global__ void k_convert(const void* __restrict__ ei) {
    int i = blockIdx.x * blockDim.x + threadIdx.x;
    int stride = gridDim.x * blockDim.x;
    const int is64 = g_is64;
    for (int e = i; e < N_EDGES; e += stride) {
        int d;
        if (is64) d = (int)((const long long*)ei)[N_EDGES + e];
        else      d = ((const int*)ei)[N_EDGES + e];
        d = min(max(d, 0), N_NODES - 1);
        atomicAdd(&g_deg[d], 1);
    }
}

// ---------------- CSR build ----------------
__global__ void k_scan1() {
    __shared__ int sh[CHUNK];
    int b = blockIdx.x, tid = threadIdx.x;
    int i = b * CHUNK + tid;
    sh[tid] = (i < N_NODES) ? g_deg[i] : 0;
    __syncthreads();
    for (int off = 64; off; off >>= 1) {
        if (tid < off) sh[tid] += sh[tid + off];
        __syncthreads();
    }
    if (tid == 0) g_part[b] = sh[0];
}

__global__ void k_scan2() {
    __shared__ int sh[1024];
    int tid = threadIdx.x;
    int v = (tid < NB) ? g_part[tid] : 0;
    sh[tid] = v;
    __syncthreads();
    for (int off = 1; off < 1024; off <<= 1) {
        int add = (tid >= off) ? sh[tid - off] : 0;
        __syncthreads();
        sh[tid] += add;
        __syncthreads();
    }
    if (tid < NB) g_partoff[tid] = sh[tid] - v;
    if (tid == 1023) g_off[N_NODES] = sh[tid];
}

__global__ void k_scan3() {
    __shared__ int sh[CHUNK];
    int b = blockIdx.x, tid = threadIdx.x;
    int i = b * CHUNK + tid;
    int v = (i < N_NODES) ? g_deg[i] : 0;
    sh[tid] = v;
    __syncthreads();
    for (int off = 1; off < CHUNK; off <<= 1) {
        int add = (tid >= off) ? sh[tid - off] : 0;
        __syncthreads();
        sh[tid] += add;
        __syncthreads();
    }
    if (i < N_NODES) {
        int excl = g_partoff[b] + sh[tid] - v;
        g_off[i] = excl;
        g_cur[i] = excl;
    }
}

// fill CSR, converting directly from edge_index; 2 edges/thread for atomic MLP
__global__ void k_fill(const void* __restrict__ ei) {
    const int HALF = (N_EDGES + 1) / 2;
    int idx = blockIdx.x * blockDim.x + threadIdx.x;
    if (idx >= HALF) return;
    const int is64 = g_is64;
    int e0 = idx, e1 = idx + HALF;
    int s0, d0, s1 = 0, d1 = 0;
    if (is64) {
        const long long* p = (const long long*)ei;
        s0 = (int)p[e0]; d0 = (int)p[N_EDGES + e0];
        if (e1 < N_EDGES) { s1 = (int)p[e1]; d1 = (int)p[N_EDGES + e1]; }
    } else {
        const int* p = (const int*)ei;
        s0 = p[e0]; d0 = p[N_EDGES + e0];
        if (e1 < N_EDGES) { s1 = p[e1]; d1 = p[N_EDGES + e1]; }
    }
    s0 = min(max(s0, 0), N_NODES - 1);
    d0 = min(max(d0, 0), N_NODES - 1);
    int pos0 = atomicAdd(&g_cur[d0], 1);
    int pos1 = -1;
    if (e1 < N_EDGES) {
        s1 = min(max(s1, 0), N_NODES - 1);
        d1 = min(max(d1, 0), N_NODES - 1);
        pos1 = atomicAdd(&g_cur[d1], 1);
    }
    g_csr_src[pos0] = s0;
    g_csr_eid[pos0] = e0;
    if (pos1 >= 0) {
        g_csr_src[pos1] = s1;
        g_csr_eid[pos1] = e1;
    }
}

// ---------------- fused SAGE-1: 16 nodes/block (2 per warp), fp16 gather ---------------
__global__ void k_sage1(const float* __restrict__ w1l, const float* __restrict__ b1,
                        const float* __restrict__ w1r) {
    __shared__ float s_wl[7][HID], s_wr[7][HID], s_b[HID];
    int tid = threadIdx.x;
    for (int j = tid; j < 7 * HID; j += 256) {
        s_wl[j >> 7][j & 127] = w1l[j];
        s_wr[j >> 7][j & 127] = w1r[j];
    }
    if (tid < HID) s_b[tid] = b1[tid];
    __syncthreads();
    int wid = tid >> 5, lane = tid & 31;
#pragma unroll 1
    for (int rep = 0; rep < 2; rep++) {
        int n = blockIdx.x * 16 + wid + rep * 8;
        if (n >= N_NODES) continue;
        int beg = g_off[n], end = g_off[n + 1];
        float a0 = 0.f, a1 = 0.f, a2 = 0.f, a3 = 0.f, a4 = 0.f, a5 = 0.f, a6 = 0.f;
        for (int i = beg + lane; i < end; i += 32) {
            int s = g_csr_src[i];
            uint4 raw = *(const uint4*)(g_x8h + (size_t)s * 8);
            float2 f0 = __half22float2(*(__half2*)&raw.x);
            float2 f1 = __half22float2(*(__half2*)&raw.y);
            float2 f2 = __half22float2(*(__half2*)&raw.z);
            float2 f3 = __half22float2(*(__half2*)&raw.w);
            a0 += f0.x; a1 += f0.y; a2 += f1.x; a3 += f1.y;
            a4 += f2.x; a5 += f2.y; a6 += f3.x;
        }
#pragma unroll
        for (int off = 16; off; off >>= 1) {
            a0 += __shfl_xor_sync(0xFFFFFFFFu, a0, off);
            a1 += __shfl_xor_sync(0xFFFFFFFFu, a1, off);
            a2 += __shfl_xor_sync(0xFFFFFFFFu, a2, off);
            a3 += __shfl_xor_sync(0xFFFFFFFFu, a3, off);
            a4 += __shfl_xor_sync(0xFFFFFFFFu, a4, off);
            a5 += __shfl_xor_sync(0xFFFFFFFFu, a5, off);
            a6 += __shfl_xor_sync(0xFFFFFFFFu, a6, off);
        }
        float inv = 1.f / fmaxf((float)(end - beg), 1.f);
        float m[7] = {a0 * inv, a1 * inv, a2 * inv, a3 * inv, a4 * inv, a5 * inv, a6 * inv};
        const float4* xp = (const float4*)(g_x8 + (size_t)n * 8);
        float4 u = xp[0];
        float4 w = xp[1];
        float xn[7] = {u.x, u.y, u.z, u.w, w.x, w.y, w.z};
#pragma unroll
        for (int j = 0; j < 4; j++) {
            int c = lane + 32 * j;
            float acc = s_b[c];
#pragma unroll
            for (int k = 0; k < 7; k++)
                acc += m[k] * s_wl[k][c] + xn[k] * s_wr[k][c];
            g_h1h[(size_t)n * HID + c] = __float2half_rn(fmaxf(acc, 0.f));
        }
    }
}

// ---------------- SAGE-2: fused mean-gather + wmma GEMM (K=256) + hg epilogue ----------
__global__ void __launch_bounds__(128) k_node2(const float* __restrict__ b2,
                                               const float* __restrict__ wg) {
    extern __shared__ __align__(16) char smem[];
    __half (*sA)[136] = (__half(*)[136])smem;               // 64 x 136
    __half (*sB)[136] = (__half(*)[136])(smem + 17408);     // 128 x 136
    float  (*sC)[136] = (float (*)[136])(smem + 17408);     // reuse
    int tid = threadIdx.x;
    int warp = tid >> 5, lane = tid & 31;
    int n0 = blockIdx.x * 64;

    // ---- prologue: gather mean(h1h[neighbors]) into sA (one warp per node, unroll 4)
    for (int r = warp; r < 64; r += 4) {
        int n = n0 + r;
        float4 acc = {0.f, 0.f, 0.f, 0.f};
        float inv = 0.f;
        if (n < N_NODES) {
            int beg = g_off[n], end = g_off[n + 1];
            int i = beg;
            for (; i + 4 <= end; i += 4) {
                int s0 = g_csr_src[i], s1 = g_csr_src[i + 1];
                int s2 = g_csr_src[i + 2], s3 = g_csr_src[i + 3];
                uint2 r0 = *(const uint2*)(g_h1h + (size_t)s0 * HID + lane * 4);
                uint2 r1 = *(const uint2*)(g_h1h + (size_t)s1 * HID + lane * 4);
                uint2 r2 = *(const uint2*)(g_h1h + (size_t)s2 * HID + lane * 4);
                uint2 r3 = *(const uint2*)(g_h1h + (size_t)s3 * HID + lane * 4);
                float2 f;
                f = __half22float2(*(__half2*)&r0.x); acc.x += f.x; acc.y += f.y;
                f = __half22float2(*(__half2*)&r0.y); acc.z += f.x; acc.w += f.y;
                f = __half22float2(*(__half2*)&r1.x); acc.x += f.x; acc.y += f.y;
                f = __half22float2(*(__half2*)&r1.y); acc.z += f.x; acc.w += f.y;
                f = __half22float2(*(__half2*)&r2.x); acc.x += f.x; acc.y += f.y;
                f = __half22float2(*(__half2*)&r2.y); acc.z += f.x; acc.w += f.y;
                f = __half22float2(*(__half2*)&r3.x); acc.x += f.x; acc.y += f.y;
                f = __half22float2(*(__half2*)&r3.y); acc.z += f.x; acc.w += f.y;
            }
            for (; i < end; i++) {
                int s = g_csr_src[i];
                uint2 r0 = *(const uint2*)(g_h1h + (size_t)s * HID + lane * 4);
                float2 f;
                f = __half22float2(*(__half2*)&r0.x); acc.x += f.x; acc.y += f.y;
                f = __half22float2(*(__half2*)&r0.y); acc.z += f.x; acc.w += f.y;
            }
            inv = 1.f / fmaxf((float)(end - beg), 1.f);
        }
        __half2 h01 = __floats2half2_rn(acc.x * inv, acc.y * inv);
        __half2 h23 = __floats2half2_rn(acc.z * inv, acc.w * inv);
        uint2 packed;
        packed.x = *(unsigned*)&h01;
        packed.y = *(unsigned*)&h23;
        *(uint2*)&sA[r][lane * 4] = packed;
    }

    wmma::fragment<wmma::accumulator, 16, 16, 16, float> c[8];
#pragma unroll
    for (int i = 0; i < 8; i++) wmma::fill_fragment(c[i], 0.f);
    wmma::fragment<wmma::matrix_a, 16, 16, 16, __half, wmma::row_major> a;
    wmma::fragment<wmma::matrix_b, 16, 16, 16, __half, wmma::row_major> b;

    // ---- kh = 0: A = mean (sA), B = w2l rows
    {
        const uint4* wsrc = (const uint4*)g_w2cat_h;
        for (int j = tid; j < 128 * 16; j += 128) {
            int r = j >> 4, c4 = j & 15;
            ((uint4*)&sB[r][0])[c4] = wsrc[(size_t)r * 16 + c4];
        }
        __syncthreads();
#pragma unroll
        for (int kt = 0; kt < 8; kt++) {
            wmma::load_matrix_sync(a, &sA[warp * 16][kt * 16], 136);
#pragma unroll
            for (int nt = 0; nt < 8; nt++) {
                wmma::load_matrix_sync(b, &sB[kt * 16][nt * 16], 136);
                wmma::mma_sync(c[nt], a, b, c[nt]);
            }
        }
        __syncthreads();
    }
    // ---- kh = 1: A = h1h rows, B = w2r rows
    {
        const uint4* asrc = (const uint4*)g_h1h;
        for (int j = tid; j < 64 * 16; j += 128) {
            int r = j >> 4, c4 = j & 15;
            ((uint4*)&sA[r][0])[c4] = asrc[(size_t)(n0 + r) * 16 + c4];
        }
        const uint4* wsrc = (const uint4*)g_w2cat_h;
        for (int j = tid; j < 128 * 16; j += 128) {
            int r = j >> 4, c4 = j & 15;
            ((uint4*)&sB[r][0])[c4] = wsrc[(size_t)(128 + r) * 16 + c4];
        }
        __syncthreads();
#pragma unroll
        for (int kt = 0; kt < 8; kt++) {
            wmma::load_matrix_sync(a, &sA[warp * 16][kt * 16], 136);
#pragma unroll
            for (int nt = 0; nt < 8; nt++) {
                wmma::load_matrix_sync(b, &sB[kt * 16][nt * 16], 136);
                wmma::mma_sync(c[nt], a, b, c[nt]);
            }
        }
        __syncthreads();
    }
#pragma unroll
    for (int nt = 0; nt < 8; nt++)
        wmma::store_matrix_sync(&sC[warp * 16][nt * 16], c[nt], 136, wmma::mem_row_major);
    __syncthreads();
    // ---- epilogue: h2h (fp16) + hg = (sC + b2) . wg
    for (int j = tid; j < 64 * 128; j += 128) {
        int r = j >> 7, cc = j & 127;
        float v = sC[r][cc] + __ldg(&b2[cc]);
        g_h2h[(size_t)(n0 + r) * HID + cc] = __float2half_rn(v);
    }
    for (int r = warp; r < 64; r += 4) {
        float part = 0.f;
#pragma unroll
        for (int j = 0; j < 4; j++) {
            int cc = lane + 32 * j;
            part += (sC[r][cc] + __ldg(&b2[cc])) * __ldg(&wg[cc]);
        }
#pragma unroll
        for (int off = 16; off; off >>= 1)
            part += __shfl_xor_sync(0xFFFFFFFFu, part, off);
        if (lane == 0 && n0 + r < N_NODES) g_hg[n0 + r] = part;
    }
}

// ---------------- t/p/q: wmma GEMMs; t folded into positions epilogue ----------------
__global__ void __launch_bounds__(128) k_tpq(const float* __restrict__ bv1,
                                             const float* __restrict__ be1,
                                             const float* __restrict__ wv2,
                                             const float* __restrict__ bv2,
                                             float* __restrict__ out_pos) {
    extern __shared__ __align__(16) char smem[];
    __half (*sA)[136] = (__half(*)[136])smem;               // 64 x 136
    __half (*sB)[136] = (__half(*)[136])(smem + 17408);     // 128 x 136
    float  (*sC)[136] = (float (*)[136])(smem + 17408);     // reuse
    int tid = threadIdx.x;
    int warp = tid >> 5, lane = tid & 31;
    int n0 = blockIdx.x * 64;

    const uint4* asrc = (const uint4*)g_h2h;
    for (int j = tid; j < 64 * 16; j += 128) {
        int r = j >> 4, c4 = j & 15;
        ((uint4*)&sA[r][0])[c4] = asrc[(size_t)(n0 + r) * 16 + c4];
    }
    __syncthreads();

    wmma::fragment<wmma::matrix_a, 16, 16, 16, __half, wmma::row_major> a[8];
#pragma unroll
    for (int kt = 0; kt < 8; kt++)
        wmma::load_matrix_sync(a[kt], &sA[warp * 16][kt * 16], 136);

#pragma unroll 1
    for (int m = 0; m < 3; m++) {
        const uint4* wsrc = (const uint4*)g_w_h[m];
        for (int j = tid; j < 128 * 16; j += 128) {
            int r = j >> 4, c4 = j & 15;
            ((uint4*)&sB[r][0])[c4] = wsrc[(size_t)r * 16 + c4];
        }
        __syncthreads();
        wmma::fragment<wmma::accumulator, 16, 16, 16, float> c[8];
#pragma unroll
        for (int i = 0; i < 8; i++) wmma::fill_fragment(c[i], 0.f);
        wmma::fragment<wmma::matrix_b, 16, 16, 16, __half, wmma::row_major> b;
#pragma unroll
        for (int kt = 0; kt < 8; kt++) {
#pragma unroll
            for (int nt = 0; nt < 8; nt++) {
                wmma::load_matrix_sync(b, &sB[kt * 16][nt * 16], 136);
                wmma::mma_sync(c[nt], a[kt], b, c[nt]);
            }
        }
        __syncthreads();
#pragma unroll
        for (int nt = 0; nt < 8; nt++)
            wmma::store_matrix_sync(&sC[warp * 16][nt * 16], c[nt], 136, wmma::mem_row_major);
        __syncthreads();
        if (m == 0) {
            // positions: pos = relu(sC + bv1) . wv2 + bv2   (t never materialized)
            for (int r = warp; r < 64; r += 4) {
                float p0 = 0.f, p1 = 0.f, p2 = 0.f;
#pragma unroll
                for (int j = 0; j < 4; j++) {
                    int cc = lane + 32 * j;
                    float tv = fmaxf(sC[r][cc] + __ldg(&bv1[cc]), 0.f);
                    p0 += tv * __ldg(&wv2[cc * 3 + 0]);
                    p1 += tv * __ldg(&wv2[cc * 3 + 1]);
                    p2 += tv * __ldg(&wv2[cc * 3 + 2]);
                }
#pragma unroll
                for (int off = 16; off; off >>= 1) {
                    p0 += __shfl_xor_sync(0xFFFFFFFFu, p0, off);
                    p1 += __shfl_xor_sync(0xFFFFFFFFu, p1, off);
                    p2 += __shfl_xor_sync(0xFFFFFFFFu, p2, off);
                }
                int n = n0 + r;
                if (lane == 0 && n < N_NODES) {
                    out_pos[n * 3 + 0] = p0 + __ldg(&bv2[0]);
                    out_pos[n * 3 + 1] = p1 + __ldg(&bv2[1]);
                    out_pos[n * 3 + 2] = p2 + __ldg(&bv2[2]);
                }
            }
        } else {
            __half* outp = (m == 1) ? g_ph : g_qh;
            const float* bias = (m == 1) ? be1 : nullptr;
            for (int j = tid; j < 64 * 128; j += 128) {
                int r = j >> 7, cc = j & 127;
                float v = sC[r][cc] + (bias ? __ldg(&bias[cc]) : 0.f);
                outp[(size_t)(n0 + r) * HID + cc] = __float2half_rn(v);
            }
        }
        __syncthreads();
    }
}

// ---------------- fused GAT + edge MLP: warp per dst node ----------------
__global__ void k_gatedge(const float* __restrict__ att_src, const float* __restrict__ att_dst,
                          const float* __restrict__ bg, const float* __restrict__ we2,
                          const float* __restrict__ be2,
                          float* __restrict__ out_ew, float* __restrict__ out_conn) {
    int gt = blockIdx.x * blockDim.x + threadIdx.x;
    int n = gt >> 5;
    if (n >= N_NODES) return;
    int lane = gt & 31;
    int sub = lane >> 4, l = lane & 15;
    unsigned halfmask = sub ? 0xFFFF0000u : 0x0000FFFFu;

    uint4 qraw = *(const uint4*)(g_qh + (size_t)n * HID + l * 8);   // 8 halves
    float w[8];
    {
        float4 wa = *(const float4*)&we2[l * 8];
        float4 wb = *(const float4*)&we2[l * 8 + 4];
        w[0] = wa.x; w[1] = wa.y; w[2] = wa.z; w[3] = wa.w;
        w[4] = wb.x; w[5] = wb.y; w[6] = wb.z; w[7] = wb.w;
    }
    float qf[8];
    {
        const unsigned* qr = (const unsigned*)&qraw;
#pragma unroll
        for (int j = 0; j < 4; j++) {
            float2 f = __half22float2(*(const __half2*)&qr[j]);
            qf[j * 2] = f.x; qf[j * 2 + 1] = f.y;
        }
    }
    float as_ = __ldg(att_src), ad = __ldg(att_dst);
    float hgd = g_hg[n] * ad;
    float be2v = __ldg(be2);
    int beg = g_off[n], end = g_off[n + 1];

    float mx = -3.4e38f, ssum = 0.f, aacc = 0.f;
    for (int i = beg + sub; i < end; i += 2) {
        int s = g_csr_src[i];
        uint4 praw = *(const uint4*)(g_ph + (size_t)s * HID + l * 8);
        const unsigned* pr = (const unsigned*)&praw;
        float acc = 0.f;
#pragma unroll
        for (int j = 0; j < 4; j++) {
            float2 pf = __half22float2(*(const __half2*)&pr[j]);
            acc += fmaxf(pf.x + qf[j * 2], 0.f) * w[j * 2]
                 + fmaxf(pf.y + qf[j * 2 + 1], 0.f) * w[j * 2 + 1];
        }
#pragma unroll
        for (int off = 8; off; off >>= 1)
            acc += __shfl_down_sync(halfmask, acc, off, 16);
        if (l == 0) {
            int e = g_csr_eid[i];
            out_conn[e] = 1.f / (1.f + __expf(-(acc + be2v)));
            float hs = g_hg[s];
            float v = hs * as_ + hgd;
            v = v > 0.f ? v : 0.2f * v;
            float nm = fmaxf(mx, v);
            float e1 = __expf(mx - nm);
            float e2 = __expf(v - nm);
            ssum = ssum * e1 + e2;
            aacc = aacc * e1 + e2 * hs;
            mx = nm;
        }
    }
    float om = __shfl_sync(0xFFFFFFFFu, mx, 16);
    float os = __shfl_sync(0xFFFFFFFFu, ssum, 16);
    float oa = __shfl_sync(0xFFFFFFFFu, aacc, 16);
    if (lane == 0) {
        float nm = fmaxf(mx, om);
        float e1 = __expf(mx - nm);
        float e2 = __expf(om - nm);
        float s = ssum * e1 + os * e2;
        float a = aacc * e1 + oa * e2;
        out_ew[n] = a / (s + 1e-16f) + __ldg(bg);
    }
}

// ---------------- launcher ----------------
extern "C" void kernel_launch(void* const* d_in, const int* in_sizes, int n_in,
                              void* d_out, int out_size) {
    (void)in_sizes; (void)n_in; (void)out_size;
    const float* x  = (const float*)d_in[0];
    const void*  ei = d_in[1];
    const float* w1l = (const float*)d_in[3];
    const float* b1  = (const float*)d_in[4];
    const float* w1r = (const float*)d_in[5];
    const float* w2l = (const float*)d_in[6];
    const float* b2  = (const float*)d_in[7];
    const float* w2r = (const float*)d_in[8];
    const float* wg  = (const float*)d_in[9];
    const float* att_src = (const float*)d_in[10];
    const float* att_dst = (const float*)d_in[11];
    const float* bg  = (const float*)d_in[12];
    const float* wv1 = (const float*)d_in[13];
    const float* bv1 = (const float*)d_in[14];
    const float* wv2 = (const float*)d_in[15];
    const float* bv2 = (const float*)d_in[16];
    const float* we1 = (const float*)d_in[17];
    const float* be1 = (const float*)d_in[18];
    const float* we2 = (const float*)d_in[19];
    const float* be2 = (const float*)d_in[20];

    float* out      = (float*)d_out;
    float* out_pos  = out;                         // [N,3]
    float* out_conn = out + N_NODES * 3;           // [E,1]
    float* out_ew   = out + N_NODES * 3 + N_EDGES; // [N,1]

    cudaFuncSetAttribute(k_node2, cudaFuncAttributeMaxDynamicSharedMemorySize, GEMM_SMEM);
    cudaFuncSetAttribute(k_tpq,   cudaFuncAttributeMaxDynamicSharedMemorySize, GEMM_SMEM);

    const int T = 256;
    k_setup<<<512, T>>>(x, (const int*)ei, w2l, w2r, wv1, we1);
    k_convert<<<2048, T>>>(ei);

    // CSR build
    k_scan1<<<NB, CHUNK>>>();
    k_scan2<<<1, 1024>>>();
    k_scan3<<<NB, CHUNK>>>();
    k_fill<<<((N_EDGES + 1) / 2 + T - 1) / T, T>>>(ei);

    // SAGE-1 fused (16 nodes/block)
    k_sage1<<<(N_NODES + 15) / 16, 256>>>(w1l, b1, w1r);

    // SAGE-2 (mean gather + GEMM + hg fused)
    k_node2<<<NPAD / 64, 128, GEMM_SMEM>>>(b2, wg);

    // t/p/q GEMMs (positions fused into epilogue)
    k_tpq<<<NPAD / 64, 128, GEMM_SMEM>>>(bv1, be1, wv2, bv2, out_pos);

    // GAT + edge MLP fused
    k_gatedge<<<(N_NODES * 32 + T - 1) / T, T>>>(att_src, att_dst, bg, we2, be2,
                                                 out_ew, out_conn);
}